// round 13
// baseline (speedup 1.0000x reference)
#include <cuda_runtime.h>
#include <cstdint>

// Analytical collapse of the reference:
//   q = x @ Wq^T + bq ;  c_w = cos(q_w + phi_w)
//   o[0] = c1*...*c7 ;  o[w] = c0*...*cw  (w=1..7)   [CNOT-ring Z expectations]
//   y = o @ Wc^T + bc
// k/v dead. FFMA2 GEMVs, tree prefix products.
// 128 blocks x 128 threads x 2 rows/thread = 32768 rows exactly (no guards).

#define E 8

__device__ __forceinline__ unsigned long long pack2(float lo, float hi) {
    unsigned long long r;
    asm("mov.b64 %0, {%1, %2};" : "=l"(r) : "f"(lo), "f"(hi));
    return r;
}
__device__ __forceinline__ void unpack2(unsigned long long v, float& lo, float& hi) {
    asm("mov.b64 {%0, %1}, %2;" : "=f"(lo), "=f"(hi) : "l"(v));
}
__device__ __forceinline__ unsigned long long ffma2(unsigned long long a,
                                                    unsigned long long b,
                                                    unsigned long long c) {
    unsigned long long r;
    asm("fma.rn.f32x2 %0, %1, %2, %3;" : "=l"(r) : "l"(a), "l"(b), "l"(c));
    return r;
}

struct Row { float v[E]; };

__device__ __forceinline__ void body(const float* xr,
                                     const unsigned long long* sWq2,
                                     const unsigned long long* sWc2,
                                     const unsigned long long* sbqp2,
                                     const unsigned long long* sbc2,
                                     float* y)
{
    unsigned long long acc[4];
#pragma unroll
    for (int jp = 0; jp < 4; jp++) acc[jp] = sbqp2[jp];
#pragma unroll
    for (int k = 0; k < E; k++) {
        unsigned long long xk = pack2(xr[k], xr[k]);
#pragma unroll
        for (int jp = 0; jp < 4; jp++)
            acc[jp] = ffma2(xk, sWq2[k * 4 + jp], acc[jp]);
    }

    float c[E];
#pragma unroll
    for (int jp = 0; jp < 4; jp++) {
        float q0, q1;
        unpack2(acc[jp], q0, q1);
        c[2 * jp]     = __cosf(q0);
        c[2 * jp + 1] = __cosf(q1);
    }

    // Prefix products, balanced tree (depth 4)
    float p01 = c[0] * c[1];
    float p23 = c[2] * c[3];
    float p45 = c[4] * c[5];
    float p67 = c[6] * c[7];
    float p03 = p01 * p23;
    float p47 = p45 * p67;

    float o[E];
    o[1] = p01;
    o[2] = p01 * c[2];
    o[3] = p03;
    o[4] = p03 * c[4];
    o[5] = p03 * p45;
    o[6] = o[5] * c[6];
    o[7] = p03 * p47;
    o[0] = (c[1] * p23) * p47;

    unsigned long long acc2[4];
#pragma unroll
    for (int jp = 0; jp < 4; jp++) acc2[jp] = sbc2[jp];
#pragma unroll
    for (int k = 0; k < E; k++) {
        unsigned long long ok = pack2(o[k], o[k]);
#pragma unroll
        for (int jp = 0; jp < 4; jp++)
            acc2[jp] = ffma2(ok, sWc2[k * 4 + jp], acc2[jp]);
    }
#pragma unroll
    for (int jp = 0; jp < 4; jp++)
        unpack2(acc2[jp], y[2 * jp], y[2 * jp + 1]);
}

__global__ __launch_bounds__(128)
void mhaq_kernel(const float* __restrict__ x,
                 const float* __restrict__ Wq,
                 const float* __restrict__ bq,
                 const float* __restrict__ Wc,
                 const float* __restrict__ bc,
                 const float* __restrict__ phi,
                 float* __restrict__ out)
{
    // Transposed pair layout: sW[k*4 + jp] = (W[2jp, k], W[2jp+1, k])
    __shared__ unsigned long long sWq2[32];
    __shared__ unsigned long long sWc2[32];
    __shared__ unsigned long long sbqp2[4];   // (bq+phi) pairs
    __shared__ unsigned long long sbc2[4];

    int t = threadIdx.x;
    int row0 = blockIdx.x * 256 + t;      // rows [blk*256 + t] and [+128]
    int row1 = row0 + 128;

    // Issue both row loads first: 4 independent LDG.128 in flight
    const float4* xp0 = reinterpret_cast<const float4*>(x) + (size_t)row0 * 2;
    const float4* xp1 = reinterpret_cast<const float4*>(x) + (size_t)row1 * 2;
    float4 a0 = xp0[0];
    float4 b0 = xp0[1];
    float4 a1 = xp1[0];
    float4 b1 = xp1[1];

    {
        int m = t & 63;                 // element within an 8x8 matrix
        int j = m >> 3, k = m & 7;
        int slot = (k * 4 + (j >> 1)) * 2 + (j & 1);
        if (t < 64) reinterpret_cast<float*>(sWq2)[slot] = Wq[m];
        else        reinterpret_cast<float*>(sWc2)[slot] = Wc[m];
    }
    if (t < 8) {
        reinterpret_cast<float*>(sbqp2)[t] = bq[t] + phi[t];
        reinterpret_cast<float*>(sbc2)[t]  = bc[t];
    }
    __syncthreads();

    float xr0[E] = {a0.x, a0.y, a0.z, a0.w, b0.x, b0.y, b0.z, b0.w};
    float xr1[E] = {a1.x, a1.y, a1.z, a1.w, b1.x, b1.y, b1.z, b1.w};

    float y0[E], y1[E];
    body(xr0, sWq2, sWc2, sbqp2, sbc2, y0);
    body(xr1, sWq2, sWc2, sbqp2, sbc2, y1);

    float4* op0 = reinterpret_cast<float4*>(out) + (size_t)row0 * 2;
    float4* op1 = reinterpret_cast<float4*>(out) + (size_t)row1 * 2;
    op0[0] = make_float4(y0[0], y0[1], y0[2], y0[3]);
    op0[1] = make_float4(y0[4], y0[5], y0[6], y0[7]);
    op1[0] = make_float4(y1[0], y1[1], y1[2], y1[3]);
    op1[1] = make_float4(y1[4], y1[5], y1[6], y1[7]);
}

extern "C" void kernel_launch(void* const* d_in, const int* in_sizes, int n_in,
                              void* d_out, int out_size)
{
    // metadata order: x, Wq, bq, Wk, bk, Wv, bv, Wc, bc, phi
    const float* x   = (const float*)d_in[0];
    const float* Wq  = (const float*)d_in[1];
    const float* bq  = (const float*)d_in[2];
    const float* Wc  = (const float*)d_in[7];
    const float* bc  = (const float*)d_in[8];
    const float* phi = (const float*)d_in[9];
    float* out = (float*)d_out;

    int n_rows = in_sizes[0] / E;            // 32768
    int blocks = n_rows / 256;               // 128 blocks x 128 threads x 2 rows
    mhaq_kernel<<<blocks, 128>>>(x, Wq, bq, Wc, bc, phi, out);
}